// round 6
// baseline (speedup 1.0000x reference)
#include <cuda_runtime.h>
#include <math.h>
#include <stdint.h>

#define NLEV 16
#define THASH (1u << 19)
#define EBLK 256           // encode block
#define MBLK 256           // mlp block: 256 points/CTA, k-split across 2 halves
#define NMAX (1 << 20)
#define ACT_STRIDE 68      // 17 float4 -> conflict-free LDS.128
#define WTOT 10436         // 2048 + 4096 + 4096 + 192 + 4

struct Res4 { int v[NLEV][4]; };

// Feature scratch, level-major for coalesced writes (A) and reads (B).
__device__ float2 g_feat[NLEV][NMAX];

// ---- packed f32x2 helpers -------------------------------------------------
__device__ __forceinline__ void fma2(unsigned long long& d,
                                     unsigned long long a,
                                     unsigned long long b) {
    asm("fma.rn.f32x2 %0, %1, %2, %0;" : "+l"(d) : "l"(a), "l"(b));
}
__device__ __forceinline__ float2 upk(unsigned long long v) {
    float2 r; asm("mov.b64 {%0,%1}, %2;" : "=f"(r.x), "=f"(r.y) : "l"(v)); return r;
}

// ---------------------------------------------------------------------------
// Kernel A: multi-res 4D hash encode. L2-sector bound; unchanged (proven).
// ---------------------------------------------------------------------------
__global__ void __launch_bounds__(EBLK, 4)
ingp_encode(const float4* __restrict__ x,
            const float2* __restrict__ table,
            int N, Res4 res)
{
    const int n = blockIdx.x * EBLK + threadIdx.x;
    if (n >= N) return;
    const float4 xv = __ldg(x + n);

    #pragma unroll 1
    for (int l = 0; l < NLEV; l++) {
        const float r0 = (float)res.v[l][0] - 1.0f;
        const float r1 = (float)res.v[l][1] - 1.0f;
        const float r2 = (float)res.v[l][2] - 1.0f;
        const float r3 = (float)res.v[l][3] - 1.0f;
        float p0 = xv.x * r0, p1 = xv.y * r1, p2 = xv.z * r2, p3 = xv.w * r3;
        float b0 = floorf(p0), b1 = floorf(p1), b2 = floorf(p2), b3 = floorf(p3);
        float f0 = p0 - b0, f1 = p1 - b1, f2 = p2 - b2, f3 = p3 - b3;
        float g0 = 1.f - f0, g1 = 1.f - f1, g2 = 1.f - f2, g3 = 1.f - f3;

        unsigned ha0 = (unsigned)(int)b0;                 unsigned hb0 = ha0 + 1u;
        unsigned ha1 = (unsigned)(int)b1 * 2654435761u;   unsigned hb1 = ha1 + 2654435761u;
        unsigned ha2 = (unsigned)(int)b2 * 805459861u;    unsigned hb2 = ha2 + 805459861u;
        unsigned ha3 = (unsigned)(int)b3 * 3674653429u;   unsigned hb3 = ha3 + 3674653429u;

        unsigned hxy[4] = { ha0 ^ ha1, hb0 ^ ha1, ha0 ^ hb1, hb0 ^ hb1 };
        unsigned hzw[4] = { ha2 ^ ha3, hb2 ^ ha3, ha2 ^ hb3, hb2 ^ hb3 };
        float    wxy[4] = { g0 * g1,  f0 * g1,  g0 * f1,  f0 * f1 };
        float    wzw[4] = { g2 * g3,  f2 * g3,  g2 * f3,  f2 * f3 };

        const float2* tl = table + ((size_t)l << 19);
        float acc0 = 0.f, acc1 = 0.f;
        #pragma unroll
        for (int c = 0; c < 16; c++) {
            unsigned idx = (hxy[c & 3] ^ hzw[(c >> 2) & 3]) & (THASH - 1u);
            float2 t2 = __ldg(tl + idx);
            float w = wxy[c & 3] * wzw[(c >> 2) & 3];
            acc0 = fmaf(w, t2.x, acc0);
            acc1 = fmaf(w, t2.y, acc1);
        }
        g_feat[l][n] = make_float2(acc0, acc1);
    }
}

// ---------------------------------------------------------------------------
// Kernel B: MLP with k-split. 256 threads, 256 points per CTA.
// Thread (p, h): points (p, p+128), k-half h. fin regs halve -> ~115 regs ->
// 2 CTAs x 8 warps = 16 warps/SM. Partials combine through staging rows.
// ---------------------------------------------------------------------------
__global__ void __launch_bounds__(MBLK, 2)
ingp_mlp(const float* __restrict__ w0,
         const float* __restrict__ w1,
         const float* __restrict__ w2,
         const float* __restrict__ w_out,
         const float* __restrict__ b_out,
         float* __restrict__ out, int N)
{
    extern __shared__ float sm[];
    float* s_w0 = sm;                       // [64][32]
    float* s_w1 = sm + 2048;                // [64][64]
    float* s_w2 = sm + 6144;                // [64][64]
    float* s_wo = sm + 10240;               // [3][64]
    float* s_bo = sm + 10432;               // 3 (+pad)
    float* s_act = sm + WTOT;               // 256 * ACT_STRIDE

    const int tid = threadIdx.x;

    {   // cooperative weight load
        float4* dw0 = (float4*)s_w0; const float4* sw0 = (const float4*)w0;
        float4* dw1 = (float4*)s_w1; const float4* sw1 = (const float4*)w1;
        float4* dw2 = (float4*)s_w2; const float4* sw2 = (const float4*)w2;
        float4* dwo = (float4*)s_wo; const float4* swo = (const float4*)w_out;
        #pragma unroll 1
        for (int i = tid; i < 512;  i += MBLK) dw0[i] = sw0[i];
        #pragma unroll 1
        for (int i = tid; i < 1024; i += MBLK) dw1[i] = sw1[i];
        #pragma unroll 1
        for (int i = tid; i < 1024; i += MBLK) dw2[i] = sw2[i];
        if (tid < 48) dwo[tid] = swo[tid];
        if (tid < 3)  s_bo[tid] = b_out[tid];
    }
    __syncthreads();

    const int h = tid >> 7;          // k-half (0 or 1)
    const int p = tid & 127;         // local point index
    const int n0 = blockIdx.x * MBLK;
    if (n0 >= N) return;
    const int nA = n0 + p;
    const int nB = nA + 128;

    float* arowA = s_act + p * ACT_STRIDE;
    float* arowB = s_act + (p + 128) * ACT_STRIDE;
    float4* a4A = (float4*)arowA;
    float4* a4B = (float4*)arowB;

    unsigned long long finA[16], finB[16];

    // features for own k-half: levels [8h, 8h+8)
    #pragma unroll
    for (int i = 0; i < 8; i++) {
        const int l = 8 * h + i;
        finA[i] = __ldg((const unsigned long long*)&g_feat[l][nA]);
        finB[i] = __ldg((const unsigned long long*)&g_feat[l][nB]);
    }

    // ---- layer 0: 32 -> 64, ReLU (k-half = 16 inputs -> 4 ull2 per row) ----
    #pragma unroll 1
    for (int j = 0; j < 64; j += 4) {
        unsigned long long a0 = 0, a1 = 0, a2 = 0, a3 = 0;
        unsigned long long c0 = 0, c1 = 0, c2 = 0, c3 = 0;
        const ulonglong2* r0 = (const ulonglong2*)(s_w0 + (j + 0) * 32 + h * 16);
        const ulonglong2* r1 = (const ulonglong2*)(s_w0 + (j + 1) * 32 + h * 16);
        const ulonglong2* r2 = (const ulonglong2*)(s_w0 + (j + 2) * 32 + h * 16);
        const ulonglong2* r3 = (const ulonglong2*)(s_w0 + (j + 3) * 32 + h * 16);
        #pragma unroll
        for (int q = 0; q < 4; q++) {
            unsigned long long pA0 = finA[2*q], pA1 = finA[2*q+1];
            unsigned long long pB0 = finB[2*q], pB1 = finB[2*q+1];
            ulonglong2 wa = r0[q];
            fma2(a0, pA0, wa.x); fma2(a0, pA1, wa.y);
            fma2(c0, pB0, wa.x); fma2(c0, pB1, wa.y);
            ulonglong2 wb = r1[q];
            fma2(a1, pA0, wb.x); fma2(a1, pA1, wb.y);
            fma2(c1, pB0, wb.x); fma2(c1, pB1, wb.y);
            ulonglong2 wc = r2[q];
            fma2(a2, pA0, wc.x); fma2(a2, pA1, wc.y);
            fma2(c2, pB0, wc.x); fma2(c2, pB1, wc.y);
            ulonglong2 wd = r3[q];
            fma2(a3, pA0, wd.x); fma2(a3, pA1, wd.y);
            fma2(c3, pB0, wd.x); fma2(c3, pB1, wd.y);
        }
        float2 s0 = upk(a0), s1 = upk(a1), s2 = upk(a2), s3 = upk(a3);
        float2 t0 = upk(c0), t1 = upk(c1), t2 = upk(c2), t3 = upk(c3);
        float sA0 = s0.x + s0.y, sA1 = s1.x + s1.y, sA2 = s2.x + s2.y, sA3 = s3.x + s3.y;
        float sB0 = t0.x + t0.y, sB1 = t1.x + t1.y, sB2 = t2.x + t2.y, sB3 = t3.x + t3.y;
        if (h == 0) {
            a4A[j >> 2] = make_float4(sA0, sA1, sA2, sA3);   // partial
            a4B[j >> 2] = make_float4(sB0, sB1, sB2, sB3);
        }
        __syncthreads();
        if (h == 1) {
            float4 pa = a4A[j >> 2];
            a4A[j >> 2] = make_float4(fmaxf(pa.x + sA0, 0.f), fmaxf(pa.y + sA1, 0.f),
                                      fmaxf(pa.z + sA2, 0.f), fmaxf(pa.w + sA3, 0.f));
            float4 pb = a4B[j >> 2];
            a4B[j >> 2] = make_float4(fmaxf(pb.x + sB0, 0.f), fmaxf(pb.y + sB1, 0.f),
                                      fmaxf(pb.z + sB2, 0.f), fmaxf(pb.w + sB3, 0.f));
        }
    }
    __syncthreads();

    // ---- layers 1 & 2: 64 -> 64, ReLU (k-half = 32 inputs -> 8 ull2/row) ----
    #pragma unroll 1
    for (int layer = 0; layer < 2; layer++) {
        const float* s_w = (layer == 0) ? s_w1 : s_w2;
        // reload own k-half of activations
        #pragma unroll
        for (int q = 0; q < 8; q++) {
            ulonglong2 vA = ((const ulonglong2*)(arowA + 32 * h))[q];
            ulonglong2 vB = ((const ulonglong2*)(arowB + 32 * h))[q];
            finA[2*q] = vA.x; finA[2*q+1] = vA.y;
            finB[2*q] = vB.x; finB[2*q+1] = vB.y;
        }
        __syncthreads();   // all reads done before partials overwrite rows
        #pragma unroll 1
        for (int j = 0; j < 64; j += 4) {
            unsigned long long a0 = 0, a1 = 0, a2 = 0, a3 = 0;
            unsigned long long c0 = 0, c1 = 0, c2 = 0, c3 = 0;
            const ulonglong2* r0 = (const ulonglong2*)(s_w + (j + 0) * 64 + h * 32);
            const ulonglong2* r1 = (const ulonglong2*)(s_w + (j + 1) * 64 + h * 32);
            const ulonglong2* r2 = (const ulonglong2*)(s_w + (j + 2) * 64 + h * 32);
            const ulonglong2* r3 = (const ulonglong2*)(s_w + (j + 3) * 64 + h * 32);
            #pragma unroll
            for (int q = 0; q < 8; q++) {
                unsigned long long pA0 = finA[2*q], pA1 = finA[2*q+1];
                unsigned long long pB0 = finB[2*q], pB1 = finB[2*q+1];
                ulonglong2 wa = r0[q];
                fma2(a0, pA0, wa.x); fma2(a0, pA1, wa.y);
                fma2(c0, pB0, wa.x); fma2(c0, pB1, wa.y);
                ulonglong2 wb = r1[q];
                fma2(a1, pA0, wb.x); fma2(a1, pA1, wb.y);
                fma2(c1, pB0, wb.x); fma2(c1, pB1, wb.y);
                ulonglong2 wc = r2[q];
                fma2(a2, pA0, wc.x); fma2(a2, pA1, wc.y);
                fma2(c2, pB0, wc.x); fma2(c2, pB1, wc.y);
                ulonglong2 wd = r3[q];
                fma2(a3, pA0, wd.x); fma2(a3, pA1, wd.y);
                fma2(c3, pB0, wd.x); fma2(c3, pB1, wd.y);
            }
            float2 s0 = upk(a0), s1 = upk(a1), s2 = upk(a2), s3 = upk(a3);
            float2 t0 = upk(c0), t1 = upk(c1), t2 = upk(c2), t3 = upk(c3);
            float sA0 = s0.x + s0.y, sA1 = s1.x + s1.y, sA2 = s2.x + s2.y, sA3 = s3.x + s3.y;
            float sB0 = t0.x + t0.y, sB1 = t1.x + t1.y, sB2 = t2.x + t2.y, sB3 = t3.x + t3.y;
            if (h == 0) {
                a4A[j >> 2] = make_float4(sA0, sA1, sA2, sA3);
                a4B[j >> 2] = make_float4(sB0, sB1, sB2, sB3);
            }
            __syncthreads();
            if (h == 1) {
                float4 pa = a4A[j >> 2];
                a4A[j >> 2] = make_float4(fmaxf(pa.x + sA0, 0.f), fmaxf(pa.y + sA1, 0.f),
                                          fmaxf(pa.z + sA2, 0.f), fmaxf(pa.w + sA3, 0.f));
                float4 pb = a4B[j >> 2];
                a4B[j >> 2] = make_float4(fmaxf(pb.x + sB0, 0.f), fmaxf(pb.y + sB1, 0.f),
                                          fmaxf(pb.z + sB2, 0.f), fmaxf(pb.w + sB3, 0.f));
            }
        }
        __syncthreads();
    }

    // ---- output layer: 64 -> 3, + bias ----
    #pragma unroll
    for (int q = 0; q < 8; q++) {
        ulonglong2 vA = ((const ulonglong2*)(arowA + 32 * h))[q];
        ulonglong2 vB = ((const ulonglong2*)(arowB + 32 * h))[q];
        finA[2*q] = vA.x; finA[2*q+1] = vA.y;
        finB[2*q] = vB.x; finB[2*q+1] = vB.y;
    }
    __syncthreads();
    {
        unsigned long long a0 = 0, a1 = 0, a2 = 0;
        unsigned long long c0 = 0, c1 = 0, c2 = 0;
        const ulonglong2* r0 = (const ulonglong2*)(s_wo + 0   + h * 32);
        const ulonglong2* r1 = (const ulonglong2*)(s_wo + 64  + h * 32);
        const ulonglong2* r2 = (const ulonglong2*)(s_wo + 128 + h * 32);
        #pragma unroll
        for (int q = 0; q < 8; q++) {
            unsigned long long pA0 = finA[2*q], pA1 = finA[2*q+1];
            unsigned long long pB0 = finB[2*q], pB1 = finB[2*q+1];
            ulonglong2 wa = r0[q];
            fma2(a0, pA0, wa.x); fma2(a0, pA1, wa.y);
            fma2(c0, pB0, wa.x); fma2(c0, pB1, wa.y);
            ulonglong2 wb = r1[q];
            fma2(a1, pA0, wb.x); fma2(a1, pA1, wb.y);
            fma2(c1, pB0, wb.x); fma2(c1, pB1, wb.y);
            ulonglong2 wc = r2[q];
            fma2(a2, pA0, wc.x); fma2(a2, pA1, wc.y);
            fma2(c2, pB0, wc.x); fma2(c2, pB1, wc.y);
        }
        float2 s0 = upk(a0), s1 = upk(a1), s2 = upk(a2);
        float2 t0 = upk(c0), t1 = upk(c1), t2 = upk(c2);
        float oA0 = s0.x + s0.y, oA1 = s1.x + s1.y, oA2 = s2.x + s2.y;
        float oB0 = t0.x + t0.y, oB1 = t1.x + t1.y, oB2 = t2.x + t2.y;
        if (h == 0) {
            a4A[0] = make_float4(oA0, oA1, oA2, 0.f);
            a4B[0] = make_float4(oB0, oB1, oB2, 0.f);
        }
        __syncthreads();
        if (h == 1) {
            const float bo0 = s_bo[0], bo1 = s_bo[1], bo2 = s_bo[2];
            float4 pa = a4A[0];
            size_t obA = (size_t)nA * 3;
            out[obA + 0] = bo0 + pa.x + oA0;
            out[obA + 1] = bo1 + pa.y + oA1;
            out[obA + 2] = bo2 + pa.z + oA2;
            float4 pb = a4B[0];
            size_t obB = (size_t)nB * 3;
            out[obB + 0] = bo0 + pb.x + oB0;
            out[obB + 1] = bo1 + pb.y + oB1;
            out[obB + 2] = bo2 + pb.z + oB2;
        }
    }
}

extern "C" void kernel_launch(void* const* d_in, const int* in_sizes, int n_in,
                              void* d_out, int out_size)
{
    const float4* x     = (const float4*)d_in[0];
    const float2* table = (const float2*)d_in[1];
    const float*  w0    = (const float*)d_in[2];
    const float*  w1    = (const float*)d_in[3];
    const float*  w2    = (const float*)d_in[4];
    const float*  w_out = (const float*)d_in[5];
    const float*  b_out = (const float*)d_in[6];
    float* out = (float*)d_out;
    const int N = in_sizes[0] / 4;

    // Replicate numpy's RES computation bit-exactly (same aarch64 glibc pow/floor).
    Res4 res;
    const double minr[4] = {16.0, 16.0, 16.0, 16.0};
    const double maxr[4] = {256.0, 256.0, 256.0, 128.0};
    for (int d = 0; d < 4; d++) {
        double g = pow(maxr[d] / minr[d], 1.0 / 15.0);
        for (int l = 0; l < NLEV; l++) {
            res.v[l][d] = (int)floor(minr[d] * pow(g, (double)l));
        }
    }

    size_t smem = (size_t)(WTOT + MBLK * ACT_STRIDE) * sizeof(float);
    cudaFuncSetAttribute(ingp_mlp, cudaFuncAttributeMaxDynamicSharedMemorySize, (int)smem);

    int egrid = (N + EBLK - 1) / EBLK;
    ingp_encode<<<egrid, EBLK>>>(x, table, N, res);
    int mgrid = (N + MBLK - 1) / MBLK;
    ingp_mlp<<<mgrid, MBLK, smem>>>(w0, w1, w2, w_out, b_out, out, N);
}